// round 2
// baseline (speedup 1.0000x reference)
#include <cuda_runtime.h>
#include <math.h>

#define BATCH 4
#define CIN   512
#define HID   64
#define NCLS  11
#define H1    60
#define W1    80
#define P1    (H1*W1)      // 4800
#define H2    30
#define W2    40
#define P2    (H2*W2)      // 1200
#define HO    480
#define WO    640
#define PO    (HO*WO)      // 307200
#define THRESH 500

#define PROB_ELEMS ((size_t)BATCH*NCLS*PO)   // 13,516,800
#define SEG_ELEMS  ((size_t)BATCH*PO)        // 1,228,800

// -------- scratch (no allocations allowed) --------
__device__ float g_f1[BATCH*HID*P1];
__device__ float g_f2[BATCH*HID*P2];
__device__ float g_ls[BATCH*NCLS*P1];
__device__ int g_cnt[36], g_minx[36], g_maxx[36], g_miny[36], g_maxy[36];

// packed fp32x2 FMA (sm_100+): doubles fp32 throughput per issue slot
__device__ __forceinline__ float2 ffma2(float2 a, float2 b, float2 c) {
    float2 d;
    asm("fma.rn.f32x2 %0, %1, %2, %3;"
        : "=l"(*(unsigned long long*)&d)
        : "l"(*(unsigned long long*)&a),
          "l"(*(unsigned long long*)&b),
          "l"(*(unsigned long long*)&c));
    return d;
}

// ============================================================
// Stage 1: 1x1 conv (GEMM: out[b,o,p] = sum_c w[o,c]*in[b,c,p]) + bias + relu
// Tile: 128 pixels x 64 out-channels, BK=32. 256 threads.
// Thread: 8 pixels (as 4 f32x2 pairs) x 4 channels = 32 acc (16 float2).
// ============================================================
__device__ __forceinline__ void conv_gemm(
    const float* __restrict__ in, const float* __restrict__ w,
    const float* __restrict__ bias, float* __restrict__ out,
    int P, int p0, int b)
{
    __shared__ float  As[32][128];   // [k][pixel]
    __shared__ float2 Bs[32][66];    // [k][oc], weight duplicated (w,w); pad 66 for banks/alignment

    const int tid = threadIdx.x;
    const int tp  = tid & 15;        // pixel group 0..15
    const int to  = tid >> 4;        // channel group 0..15
    const float* inb = in + (size_t)b * CIN * P;

    float2 acc[4][4];
#pragma unroll
    for (int i = 0; i < 4; i++)
#pragma unroll
        for (int j = 0; j < 4; j++) acc[i][j] = make_float2(0.f, 0.f);

    for (int k0 = 0; k0 < CIN; k0 += 32) {
        __syncthreads();
        // load A tile: 32 rows x 128 pixels (clamped at pixel tail)
#pragma unroll
        for (int q = 0; q < 16; q++) {
            int l   = tid + q * 256;
            int row = l >> 7;
            int col = l & 127;
            int gp  = p0 + col;
            if (gp >= P) gp = P - 1;
            As[row][col] = inb[(size_t)(k0 + row) * P + gp];
        }
        // load B tile: 64 oc x 32 k, duplicated into float2
#pragma unroll
        for (int q = 0; q < 8; q++) {
            int l  = tid + q * 256;
            int kk = l & 31;
            int o  = l >> 5;
            float v = w[o * CIN + k0 + kk];
            Bs[kk][o] = make_float2(v, v);
        }
        __syncthreads();

#pragma unroll
        for (int kk = 0; kk < 32; kk++) {
            float4 a0 = *(const float4*)&As[kk][tp * 4];
            float4 a1 = *(const float4*)&As[kk][64 + tp * 4];
            float4 bq0 = *(const float4*)&Bs[kk][to * 4];
            float4 bq1 = *(const float4*)&Bs[kk][to * 4 + 2];
            float2 ap[4] = { {a0.x,a0.y},{a0.z,a0.w},{a1.x,a1.y},{a1.z,a1.w} };
            float2 bv[4] = { {bq0.x,bq0.y},{bq0.z,bq0.w},{bq1.x,bq1.y},{bq1.z,bq1.w} };
#pragma unroll
            for (int i = 0; i < 4; i++)
#pragma unroll
                for (int j = 0; j < 4; j++)
                    acc[i][j] = ffma2(ap[i], bv[j], acc[i][j]);
        }
    }

    float* outb = out + (size_t)b * HID * P;
#pragma unroll
    for (int j = 0; j < 4; j++) {
        int oc = to * 4 + j;
        float bo = __ldg(&bias[oc]);
        float* op = outb + (size_t)oc * P;
#pragma unroll
        for (int i = 0; i < 4; i++) {
            int px = p0 + ((i < 2) ? (tp * 4 + i * 2) : (64 + tp * 4 + (i - 2) * 2));
            if (px < P) {  // px even, P even -> px+1 also valid
                float v0 = fmaxf(acc[i][j].x + bo, 0.f);
                float v1 = fmaxf(acc[i][j].y + bo, 0.f);
                *(float2*)&op[px] = make_float2(v0, v1);
            }
        }
    }
}

__global__ void __launch_bounds__(256)
conv_both_kernel(const float* __restrict__ f1in, const float* __restrict__ f2in,
                 const float* __restrict__ w1, const float* __restrict__ b1,
                 const float* __restrict__ w2, const float* __restrict__ b2)
{
    int bx = blockIdx.x;
    int b  = blockIdx.y;
    if (bx < 38) conv_gemm(f1in, w1, b1, g_f1, P1, bx * 128, b);
    else         conv_gemm(f2in, w2, b2, g_f2, P2, (bx - 38) * 128, b);
}

// ============================================================
// Stage 2: logits_small = wc * (f1 + up2(f2)) + bc   at 60x80, 11 channels
// ============================================================
__global__ void __launch_bounds__(256)
fuse_up2_convc_kernel(const float* __restrict__ wc, const float* __restrict__ bc)
{
    __shared__ float s_wc[NCLS * HID];
    __shared__ float s_bc[NCLS];
    int tid = threadIdx.x;
    for (int i = tid; i < NCLS * HID; i += 256) s_wc[i] = wc[i];
    if (tid < NCLS) s_bc[tid] = bc[tid];
    __syncthreads();

    int p = blockIdx.x * 256 + tid;
    int b = blockIdx.y;
    if (p >= P1) return;
    int y = p / W1, x = p % W1;

    // half-pixel bilinear coords into 30x40 with edge clamp
    float fx = 0.5f * x - 0.25f;
    int ix0 = (int)floorf(fx); float tx = fx - (float)ix0;
    int ix0c = max(ix0, 0), ix1c = min(ix0 + 1, W2 - 1);
    float fy = 0.5f * y - 0.25f;
    int iy0 = (int)floorf(fy); float ty = fy - (float)iy0;
    int iy0c = max(iy0, 0), iy1c = min(iy0 + 1, H2 - 1);
    int i00 = iy0c * W2 + ix0c, i01 = iy0c * W2 + ix1c;
    int i10 = iy1c * W2 + ix0c, i11 = iy1c * W2 + ix1c;

    const float* f1b = g_f1 + (size_t)b * HID * P1 + p;
    const float* f2b = g_f2 + (size_t)b * HID * P2;

    float acc[NCLS];
#pragma unroll
    for (int c = 0; c < NCLS; c++) acc[c] = s_bc[c];

    for (int h = 0; h < HID; h++) {
        float s = f1b[(size_t)h * P1];
        const float* f2c = f2b + (size_t)h * P2;
        float v00 = f2c[i00], v01 = f2c[i01], v10 = f2c[i10], v11 = f2c[i11];
        float v0 = v00 + tx * (v01 - v00);
        float v1 = v10 + tx * (v11 - v10);
        s += v0 + ty * (v1 - v0);
#pragma unroll
        for (int c = 0; c < NCLS; c++) acc[c] = fmaf(s_wc[c * HID + h], s, acc[c]);
    }

    float* lsb = g_ls + (size_t)b * NCLS * P1 + p;
#pragma unroll
    for (int c = 0; c < NCLS; c++) lsb[(size_t)c * P1] = acc[c];
}

// ============================================================
// Stage 3: resize8(logits_small) -> softmax -> prob + argmax -> seg + bbox reduce
// block = 64x4 output pixels; needs exactly 2 input rows x 10 input cols x 11 ch
// ============================================================
__global__ void __launch_bounds__(256)
resize_softmax_kernel(float* __restrict__ out)
{
    __shared__ float st[NCLS][2][10];
    __shared__ int s_cnt[9], s_minx[9], s_maxx[9], s_miny[9], s_maxy[9];

    int tid = threadIdx.y * 64 + threadIdx.x;
    if (tid < 9) {
        s_cnt[tid] = 0;
        s_minx[tid] = 0x7fffffff; s_maxx[tid] = -1;
        s_miny[tid] = 0x7fffffff; s_maxy[tid] = -1;
    }

    int bx = blockIdx.x, by = blockIdx.y, b = blockIdx.z;
    int X0 = bx * 64, Y0 = by * 4;
    int r0 = ((Y0 + 4) >> 3) - 1;             // first needed input row (pre-clamp)
    const float* ls = g_ls + (size_t)b * NCLS * P1;

    for (int i = tid; i < NCLS * 2 * 10; i += 256) {
        int c = i / 20; int rk = i % 20; int r = rk / 10; int k = rk % 10;
        int col = min(max(bx * 8 - 1 + k, 0), W1 - 1);
        int row = min(max(r0 + r, 0), H1 - 1);
        st[c][r][k] = ls[(size_t)c * P1 + row * W1 + col];
    }
    __syncthreads();

    int X = X0 + threadIdx.x;
    int Y = Y0 + threadIdx.y;
    int jx = X & 7;
    int l0 = (threadIdx.x >> 3) + ((jx < 4) ? 0 : 1);
    float tx = (jx < 4) ? (float)(2 * jx + 9) * (1.f / 16.f)
                        : (float)(2 * jx - 7) * (1.f / 16.f);
    int jy = Y & 7;
    float ty = (jy < 4) ? (float)(2 * jy + 9) * (1.f / 16.f)
                        : (float)(2 * jy - 7) * (1.f / 16.f);
    float w00 = (1.f - ty) * (1.f - tx), w01 = (1.f - ty) * tx;
    float w10 = ty * (1.f - tx),         w11 = ty * tx;

    float L[NCLS];
    float m = -1e30f; int arg = 0;
#pragma unroll
    for (int c = 0; c < NCLS; c++) {
        float v = w00 * st[c][0][l0] + w01 * st[c][0][l0 + 1]
                + w10 * st[c][1][l0] + w11 * st[c][1][l0 + 1];
        L[c] = v;
        if (v > m) { m = v; arg = c; }   // first-max wins (matches argmax)
    }
    float ssum = 0.f;
#pragma unroll
    for (int c = 0; c < NCLS; c++) { float e = __expf(L[c] - m); L[c] = e; ssum += e; }
    float inv = 1.f / ssum;

    size_t base = (size_t)b * NCLS * PO + (size_t)Y * WO + X;
#pragma unroll
    for (int c = 0; c < NCLS; c++) out[base + (size_t)c * PO] = L[c] * inv;
    out[PROB_ELEMS + (size_t)b * PO + (size_t)Y * WO + X] = (float)arg;

    if (arg >= 1 && arg <= 9) {
        int k = arg - 1;
        atomicAdd(&s_cnt[k], 1);
        atomicMin(&s_minx[k], X); atomicMax(&s_maxx[k], X);
        atomicMin(&s_miny[k], Y); atomicMax(&s_maxy[k], Y);
    }
    __syncthreads();
    if (tid < 9 && s_cnt[tid] > 0) {
        int g = b * 9 + tid;
        atomicAdd(&g_cnt[g], s_cnt[tid]);
        atomicMin(&g_minx[g], s_minx[tid]); atomicMax(&g_maxx[g], s_maxx[tid]);
        atomicMin(&g_miny[g], s_miny[tid]); atomicMax(&g_maxy[g], s_maxy[tid]);
    }
}

// ============================================================
// bbox init / finalize
// ============================================================
__global__ void init_bbox_kernel()
{
    int t = threadIdx.x;
    if (t < 36) {
        g_cnt[t] = 0;
        g_minx[t] = 0x7fffffff; g_maxx[t] = -1;
        g_miny[t] = 0x7fffffff; g_maxy[t] = -1;
    }
}

__global__ void finalize_bbox_kernel(float* __restrict__ out)
{
    int t = threadIdx.x;
    if (t >= 36) return;
    float* row = out + PROB_ELEMS + SEG_ELEMS + (size_t)t * 6;
    int b = t / 9, k = t % 9;
    if (g_cnt[t] >= THRESH) {
        row[0] = (float)b;
        row[1] = (float)g_minx[t];
        row[2] = (float)g_miny[t];
        row[3] = (float)g_maxx[t];
        row[4] = (float)g_maxy[t];
        row[5] = (float)(k + 1);
    } else {
        row[0] = -1.f; row[1] = -1.f; row[2] = -1.f;
        row[3] = -1.f; row[4] = -1.f; row[5] = -1.f;
    }
}

// ============================================================
extern "C" void kernel_launch(void* const* d_in, const int* in_sizes, int n_in,
                              void* d_out, int out_size)
{
    const float* feature1 = (const float*)d_in[0];
    const float* feature2 = (const float*)d_in[1];
    const float* w1 = (const float*)d_in[2];
    const float* b1 = (const float*)d_in[3];
    const float* w2 = (const float*)d_in[4];
    const float* b2 = (const float*)d_in[5];
    const float* wc = (const float*)d_in[6];
    const float* bc = (const float*)d_in[7];
    float* out = (float*)d_out;

    init_bbox_kernel<<<1, 64>>>();
    conv_both_kernel<<<dim3(48, BATCH), 256>>>(feature1, feature2, w1, b1, w2, b2);
    fuse_up2_convc_kernel<<<dim3((P1 + 255) / 256, BATCH), 256>>>(wc, bc);
    resize_softmax_kernel<<<dim3(WO / 64, HO / 4, BATCH), dim3(64, 4)>>>(out);
    finalize_bbox_kernel<<<1, 64>>>(out);
}